// round 5
// baseline (speedup 1.0000x reference)
#include <cuda_runtime.h>
#include <cuda_fp16.h>
#include <cstdint>

// ---------------- problem constants ----------------
#define HSZ   2048
#define BATCH 4096
#define KDIM  4096   // COMBINED
#define NDIM  8192   // 4H

// ---------------- fp16 scratch (device globals; no allocs) ----------------
__device__ __half g_A[(size_t)BATCH * KDIM];   // combined [B, C] fp16 (h_prev | x_t)
__device__ __half g_W[(size_t)NDIM * KDIM];    // weights, rows permuted n' = 4h + g
__device__ float  g_bias[NDIM];                // bias, permuted

__device__ __forceinline__ uint32_t smem_to_u32(const void* p) {
    uint32_t a;
    asm("{ .reg .u64 t; cvta.to.shared.u64 t, %1; cvt.u32.u64 %0, t; }" : "=r"(a) : "l"(p));
    return a;
}
__device__ __forceinline__ void cp16(uint32_t dst, const void* src) {
    asm volatile("cp.async.cg.shared.global [%0], [%1], 16;\n" :: "r"(dst), "l"(src));
}
__device__ __forceinline__ void ldsm_x4(uint32_t* r, uint32_t addr) {
    asm volatile("ldmatrix.sync.aligned.m8n8.x4.shared.b16 {%0,%1,%2,%3}, [%4];"
                 : "=r"(r[0]), "=r"(r[1]), "=r"(r[2]), "=r"(r[3]) : "r"(addr));
}
__device__ __forceinline__ void mma16816(float* c, const uint32_t* a, const uint32_t* b) {
    asm volatile("mma.sync.aligned.m16n8k16.row.col.f32.f16.f16.f32 "
                 "{%0,%1,%2,%3}, {%4,%5,%6,%7}, {%8,%9}, {%0,%1,%2,%3};"
                 : "+f"(c[0]), "+f"(c[1]), "+f"(c[2]), "+f"(c[3])
                 : "r"(a[0]), "r"(a[1]), "r"(a[2]), "r"(a[3]), "r"(b[0]), "r"(b[1]));
}

// ---------------- pass 1: fp32 -> fp16 conversion ----------------
__global__ void conv_a_kernel(const float* __restrict__ x, const float* __restrict__ h) {
    int i4 = blockIdx.x * blockDim.x + threadIdx.x;     // BATCH*KDIM/4 threads
    int e = i4 << 2;
    int m = e >> 12, k = e & 4095;
    float4 v = (k < HSZ) ? *(const float4*)(h + (size_t)m * HSZ + k)
                         : *(const float4*)(x + (size_t)m * HSZ + (k - HSZ));
    __half2* dst = (__half2*)(g_A + e);
    dst[0] = __floats2half2_rn(v.x, v.y);
    dst[1] = __floats2half2_rn(v.z, v.w);
}

__global__ void conv_w_kernel(const float* __restrict__ Wf, const float* __restrict__ Wi,
                              const float* __restrict__ Wc, const float* __restrict__ Wo) {
    int i4 = blockIdx.x * blockDim.x + threadIdx.x;     // NDIM*KDIM/4 threads
    size_t e = (size_t)i4 << 2;
    int n = (int)(e >> 12), k = (int)(e & 4095);        // n' = 4h + g (permuted row)
    int g = n & 3, hh = n >> 2;
    const float* src = (g == 0) ? Wf : (g == 1) ? Wi : (g == 2) ? Wc : Wo;
    float4 v = *(const float4*)(src + (size_t)hh * KDIM + k);
    __half2* dst = (__half2*)(g_W + e);
    dst[0] = __floats2half2_rn(v.x, v.y);
    dst[1] = __floats2half2_rn(v.z, v.w);
}

__global__ void conv_b_kernel(const float* __restrict__ bf, const float* __restrict__ bi,
                              const float* __restrict__ bc, const float* __restrict__ bo) {
    int n = blockIdx.x * blockDim.x + threadIdx.x;
    if (n < NDIM) {
        int g = n & 3, hh = n >> 2;
        const float* src = (g == 0) ? bf : (g == 1) ? bi : (g == 2) ? bc : bo;
        g_bias[n] = src[hh];
    }
}

// ---------------- pass 2: mma.sync pipelined GEMM + fused LSTM epilogue ----------------
// 2 CTAs/SM: BM=128, BN=128, 256 threads, 8 warps (4x2 grid of 32x64 warp tiles)
#define BM 128
#define BN 128
#define KT 64                  // 4096 / 64
#define STAGES 3
#define STAGE_A 16384          // 128 rows x 128B
#define STAGE_BYTES 32768      // A 16KB + B 16KB
#define EPI_STRIDE 132         // floats per row (128 + 4 pad)
#define BIAS_OFF (STAGES * STAGE_BYTES)          // 98304
#define SMEM_TOTAL (BIAS_OFF + BN * 4)           // 98816 -> 2 CTAs/SM (197.6KB)

#define NTHREADS 256

__device__ __forceinline__ void load_stage(uint32_t smem_u32, int tid, int m0, int n0,
                                           int j, int s) {
    uint32_t base = smem_u32 + (uint32_t)s * STAGE_BYTES;
    int k0 = j << 6;
#pragma unroll
    for (int i = 0; i < 4; i++) {            // A: 1024 chunks of 16B
        int ch = tid + (i << 8);
        int r = ch >> 3, cc = ch & 7;
        uint32_t dst = base + (uint32_t)(r * 128 + ((cc ^ (r & 7)) << 4));
        cp16(dst, g_A + (size_t)(m0 + r) * KDIM + k0 + cc * 8);
    }
#pragma unroll
    for (int i = 0; i < 4; i++) {            // B: 1024 chunks of 16B
        int ch = tid + (i << 8);
        int r = ch >> 3, cc = ch & 7;
        uint32_t dst = base + STAGE_A + (uint32_t)(r * 128 + ((cc ^ (r & 7)) << 4));
        cp16(dst, g_W + (size_t)(n0 + r) * KDIM + k0 + cc * 8);
    }
    asm volatile("cp.async.commit_group;\n" ::: "memory");
}

__device__ __forceinline__ float sigmoidf_(float x) { return 1.0f / (1.0f + __expf(-x)); }
__device__ __forceinline__ float tanhf_(float x)    { return 2.0f / (1.0f + __expf(-2.0f * x)) - 1.0f; }

__global__ __launch_bounds__(NTHREADS, 2)
void lstm_gemm_kernel(const float* __restrict__ c_prev, float* __restrict__ out) {
    extern __shared__ char smem[];
    uint32_t smem_u32 = smem_to_u32(smem);
    float* smemf = (float*)smem;
    int tid = threadIdx.x;
    int lane = tid & 31, wid = tid >> 5;
    int wm = wid & 3, wn = wid >> 2;          // 4 x 2 warp grid, 32x64 warp tiles

    int mt = blockIdx.x & 31;                 // M-fastest: W panel stays hot in L2
    int nt = blockIdx.x >> 5;                 // 0..63
    int m0 = mt * BM, n0 = nt * BN;

    if (tid < BN / 4)
        ((float4*)(smem + BIAS_OFF))[tid] = ((const float4*)(g_bias + n0))[tid];

    // precomputed ldmatrix row offsets
    int hi = lane >> 4;                       // A k-half select
    int piece = (lane >> 3) & 1;              // B k-half select
    uint32_t aOff[2]; int aSw[2];
#pragma unroll
    for (int t4 = 0; t4 < 2; t4++) {
        int r = wm * 32 + t4 * 16 + (lane & 15);
        aOff[t4] = (uint32_t)(r * 128);
        aSw[t4] = r & 7;
    }
    uint32_t bOff[4]; int bSw[4];
#pragma unroll
    for (int p = 0; p < 4; p++) {
        int n = wn * 64 + p * 16 + (lane & 7) + ((lane >> 4) << 3);
        bOff[p] = (uint32_t)(n * 128);
        bSw[p] = n & 7;
    }

    float acc[2][8][4];
#pragma unroll
    for (int a = 0; a < 2; a++)
#pragma unroll
        for (int b = 0; b < 8; b++)
#pragma unroll
            for (int c = 0; c < 4; c++) acc[a][b][c] = 0.0f;

    load_stage(smem_u32, tid, m0, n0, 0, 0);
    load_stage(smem_u32, tid, m0, n0, 1, 1);

#pragma unroll 1
    for (int k = 0; k < KT; k++) {
        if (k < KT - 1) asm volatile("cp.async.wait_group 1;\n" ::: "memory");
        else            asm volatile("cp.async.wait_group 0;\n" ::: "memory");
        __syncthreads();
        if (k + 2 < KT) load_stage(smem_u32, tid, m0, n0, k + 2, (k + 2) % STAGES);

        uint32_t sA = smem_u32 + (uint32_t)(k % STAGES) * STAGE_BYTES;
        uint32_t sB = sA + STAGE_A;
#pragma unroll
        for (int ks = 0; ks < 4; ks++) {
            uint32_t af[2][4], bf[4][4];
#pragma unroll
            for (int t4 = 0; t4 < 2; t4++)
                ldsm_x4(af[t4], sA + aOff[t4] + (uint32_t)((((ks << 1) + hi) ^ aSw[t4]) << 4));
#pragma unroll
            for (int p = 0; p < 4; p++)
                ldsm_x4(bf[p], sB + bOff[p] + (uint32_t)((((ks << 1) + piece) ^ bSw[p]) << 4));
#pragma unroll
            for (int t4 = 0; t4 < 2; t4++)
#pragma unroll
                for (int p = 0; p < 4; p++) {
                    mma16816(acc[t4][2 * p],     af[t4], &bf[p][0]);
                    mma16816(acc[t4][2 * p + 1], af[t4], &bf[p][2]);
                }
        }
    }

    // -------- epilogue: acc -> smem (transpose to n-contiguous) --------
    __syncthreads();   // all compute done; stage smem now reusable
#pragma unroll
    for (int t4 = 0; t4 < 2; t4++) {
#pragma unroll
        for (int p = 0; p < 4; p++) {
            int r0 = wm * 32 + t4 * 16 + (lane >> 2);
            int c0 = wn * 64 + p * 16 + (lane & 3) * 2;
            *(float2*)&smemf[r0 * EPI_STRIDE + c0]            = make_float2(acc[t4][2 * p][0], acc[t4][2 * p][1]);
            *(float2*)&smemf[(r0 + 8) * EPI_STRIDE + c0]      = make_float2(acc[t4][2 * p][2], acc[t4][2 * p][3]);
            *(float2*)&smemf[r0 * EPI_STRIDE + c0 + 8]        = make_float2(acc[t4][2 * p + 1][0], acc[t4][2 * p + 1][1]);
            *(float2*)&smemf[(r0 + 8) * EPI_STRIDE + c0 + 8]  = make_float2(acc[t4][2 * p + 1][2], acc[t4][2 * p + 1][3]);
        }
    }
    __syncthreads();

    // -------- fused LSTM: gates -> h_t, c_t --------
    int r = tid >> 1;                 // 0..127 (batch row within tile)
    int hseg = tid & 1;               // half of the 32 heads
    int mrow = m0 + r;
    int hglob0 = nt * 32;             // this block's head range (BN/4 = 32 heads)
    const float* cpr = c_prev + (size_t)mrow * HSZ + hglob0;
    float* hout = out + (size_t)mrow * HSZ + hglob0;
    float* cout = out + (size_t)BATCH * HSZ + (size_t)mrow * HSZ + hglob0;
    const float* biasf = (const float*)(smem + BIAS_OFF);
#pragma unroll
    for (int g4 = 0; g4 < 4; g4++) {
        int hl = hseg * 16 + g4 * 4;                   // local head base
        float4 cp4 = *(const float4*)(cpr + hl);
        float cpv[4] = {cp4.x, cp4.y, cp4.z, cp4.w};
        float hv[4], cv[4];
#pragma unroll
        for (int j = 0; j < 4; j++) {
            const float* gt = &smemf[r * EPI_STRIDE + (hl + j) * 4];
            const float* bs = &biasf[(hl + j) * 4];
            float gf = gt[0] + bs[0];
            float gi = gt[1] + bs[1];
            float gc = gt[2] + bs[2];
            float go = gt[3] + bs[3];
            float f  = sigmoidf_(gf);
            float iv = sigmoidf_(gi);
            float ct = tanhf_(gc);
            float o  = sigmoidf_(go);
            float cn = fmaf(f, cpv[j], iv * ct);
            cv[j] = cn;
            hv[j] = o * tanhf_(cn);
        }
        *(float4*)(hout + hl) = make_float4(hv[0], hv[1], hv[2], hv[3]);
        *(float4*)(cout + hl) = make_float4(cv[0], cv[1], cv[2], cv[3]);
    }
}

// ---------------- launch ----------------
extern "C" void kernel_launch(void* const* d_in, const int* in_sizes, int n_in,
                              void* d_out, int out_size) {
    const float* x  = (const float*)d_in[0];
    const float* h  = (const float*)d_in[1];
    const float* c  = (const float*)d_in[2];
    const float* Wf = (const float*)d_in[3];
    const float* bf = (const float*)d_in[4];
    const float* Wi = (const float*)d_in[5];
    const float* bi = (const float*)d_in[6];
    const float* Wc = (const float*)d_in[7];
    const float* bc = (const float*)d_in[8];
    const float* Wo = (const float*)d_in[9];
    const float* bo = (const float*)d_in[10];
    float* out = (float*)d_out;

    conv_a_kernel<<<(BATCH * KDIM / 4) / 256, 256>>>(x, h);
    conv_w_kernel<<<(NDIM * KDIM / 4) / 256, 256>>>(Wf, Wi, Wc, Wo);
    conv_b_kernel<<<NDIM / 256, 256>>>(bf, bi, bc, bo);

    static int smem_set = 0;
    if (!smem_set) {
        cudaFuncSetAttribute(lstm_gemm_kernel,
                             cudaFuncAttributeMaxDynamicSharedMemorySize, SMEM_TOTAL);
        smem_set = 1;
    }
    lstm_gemm_kernel<<<(BATCH / BM) * (NDIM / BN), NTHREADS, SMEM_TOTAL>>>(c, out);
}

// round 6
// speedup vs baseline: 1.0726x; 1.0726x over previous
#include <cuda_runtime.h>
#include <cuda_fp16.h>
#include <cstdint>

// ---------------- problem constants ----------------
#define HSZ   2048
#define BATCH 4096
#define KDIM  4096   // COMBINED
#define NDIM  8192   // 4H

// ---------------- fp16 scratch (device globals; no allocs) ----------------
__device__ __half g_A[(size_t)BATCH * KDIM];   // combined [B, C] fp16 (h_prev | x_t)
__device__ __half g_W[(size_t)NDIM * KDIM];    // weights, rows permuted n' = 4h + g
__device__ float  g_bias[NDIM];                // bias, permuted

__device__ __forceinline__ uint32_t smem_to_u32(const void* p) {
    uint32_t a;
    asm("{ .reg .u64 t; cvta.to.shared.u64 t, %1; cvt.u32.u64 %0, t; }" : "=r"(a) : "l"(p));
    return a;
}
__device__ __forceinline__ void cp16(uint32_t dst, const void* src) {
    asm volatile("cp.async.cg.shared.global [%0], [%1], 16;\n" :: "r"(dst), "l"(src));
}
__device__ __forceinline__ void ldsm_x4(uint32_t* r, uint32_t addr) {
    asm volatile("ldmatrix.sync.aligned.m8n8.x4.shared.b16 {%0,%1,%2,%3}, [%4];"
                 : "=r"(r[0]), "=r"(r[1]), "=r"(r[2]), "=r"(r[3]) : "r"(addr));
}
__device__ __forceinline__ void mma16816(float* c, const uint32_t* a, const uint32_t* b) {
    asm volatile("mma.sync.aligned.m16n8k16.row.col.f32.f16.f16.f32 "
                 "{%0,%1,%2,%3}, {%4,%5,%6,%7}, {%8,%9}, {%0,%1,%2,%3};"
                 : "+f"(c[0]), "+f"(c[1]), "+f"(c[2]), "+f"(c[3])
                 : "r"(a[0]), "r"(a[1]), "r"(a[2]), "r"(a[3]), "r"(b[0]), "r"(b[1]));
}

// ---------------- pass 1: fp32 -> fp16 conversion ----------------
__global__ void conv_a_kernel(const float* __restrict__ x, const float* __restrict__ h) {
    int i4 = blockIdx.x * blockDim.x + threadIdx.x;
    int e = i4 << 2;
    int m = e >> 12, k = e & 4095;
    float4 v = (k < HSZ) ? *(const float4*)(h + (size_t)m * HSZ + k)
                         : *(const float4*)(x + (size_t)m * HSZ + (k - HSZ));
    __half2* dst = (__half2*)(g_A + e);
    dst[0] = __floats2half2_rn(v.x, v.y);
    dst[1] = __floats2half2_rn(v.z, v.w);
}

__global__ void conv_w_kernel(const float* __restrict__ Wf, const float* __restrict__ Wi,
                              const float* __restrict__ Wc, const float* __restrict__ Wo) {
    int i4 = blockIdx.x * blockDim.x + threadIdx.x;
    size_t e = (size_t)i4 << 2;
    int n = (int)(e >> 12), k = (int)(e & 4095);        // n' = 4h + g (permuted row)
    int g = n & 3, hh = n >> 2;
    const float* src = (g == 0) ? Wf : (g == 1) ? Wi : (g == 2) ? Wc : Wo;
    float4 v = *(const float4*)(src + (size_t)hh * KDIM + k);
    __half2* dst = (__half2*)(g_W + e);
    dst[0] = __floats2half2_rn(v.x, v.y);
    dst[1] = __floats2half2_rn(v.z, v.w);
}

__global__ void conv_b_kernel(const float* __restrict__ bf, const float* __restrict__ bi,
                              const float* __restrict__ bc, const float* __restrict__ bo) {
    int n = blockIdx.x * blockDim.x + threadIdx.x;
    if (n < NDIM) {
        int g = n & 3, hh = n >> 2;
        const float* src = (g == 0) ? bf : (g == 1) ? bi : (g == 2) ? bc : bo;
        g_bias[n] = src[hh];
    }
}

// ---------------- pass 2: mma.sync GEMM, 64x64 warp tiles, frag pipeline ----------------
// BM=BN=128, 128 threads (4 warps, 2x2 grid of 64x64 warp tiles), 2 CTAs/SM
#define BM 128
#define BN 128
#define KT 64                  // 4096 / 64
#define STAGES 3
#define STAGE_A 16384          // 128 rows x 128B
#define STAGE_BYTES 32768      // A 16KB + B 16KB
#define EPI_STRIDE 132         // floats per row (128 + 4 pad)
#define BIAS_OFF (STAGES * STAGE_BYTES)          // 98304
#define SMEM_TOTAL (BIAS_OFF + BN * 4)           // 98816 -> 2 CTAs/SM

#define NTHREADS 128

__device__ __forceinline__ float sigmoidf_(float x) { return 1.0f / (1.0f + __expf(-x)); }
__device__ __forceinline__ float tanhf_(float x)    { return 2.0f / (1.0f + __expf(-2.0f * x)) - 1.0f; }

__global__ __launch_bounds__(NTHREADS, 2)
void lstm_gemm_kernel(const float* __restrict__ c_prev, float* __restrict__ out) {
    extern __shared__ char smem[];
    uint32_t smem_u32 = smem_to_u32(smem);
    float* smemf = (float*)smem;
    int tid = threadIdx.x;
    int lane = tid & 31, wid = tid >> 5;
    int wm = wid & 1, wn = wid >> 1;          // 2 x 2 warp grid, 64x64 warp tiles

    int mt = blockIdx.x & 31;                 // M-fastest: W panel stays hot in L2
    int nt = blockIdx.x >> 5;                 // 0..63
    int m0 = mt * BM, n0 = nt * BN;

    if (tid < BN / 4)
        ((float4*)(smem + BIAS_OFF))[tid] = ((const float4*)(g_bias + n0))[tid];

    // ---- incremental cp.async addressing: 8 chunk patterns shared by A and B ----
    uint32_t off[8], dsto[8];                 // off in halves; dsto = swizzled stage offset
#pragma unroll
    for (int i = 0; i < 8; i++) {
        int ch = tid + (i << 7);              // 0..1023
        int r = ch >> 3, cc = ch & 7;
        off[i]  = (uint32_t)(r * KDIM + cc * 8);
        dsto[i] = (uint32_t)(r * 128 + ((cc ^ (r & 7)) << 4));
    }
    const __half* baseA = g_A + (size_t)m0 * KDIM;
    const __half* baseB = g_W + (size_t)n0 * KDIM;

    // ---- ldmatrix offsets ----
    int hi = lane >> 4;                       // A k-half select
    int piece = (lane >> 3) & 1;              // B k-half select
    uint32_t aOff[4]; int aSw[4];
#pragma unroll
    for (int t4 = 0; t4 < 4; t4++) {
        int r = wm * 64 + t4 * 16 + (lane & 15);
        aOff[t4] = (uint32_t)(r * 128);
        aSw[t4] = r & 7;
    }
    uint32_t bOff[4]; int bSw[4];
#pragma unroll
    for (int p = 0; p < 4; p++) {
        int n = wn * 64 + p * 16 + (lane & 7) + ((lane >> 4) << 3);
        bOff[p] = (uint32_t)(n * 128);
        bSw[p] = n & 7;
    }

    float acc[4][8][4];
#pragma unroll
    for (int a = 0; a < 4; a++)
#pragma unroll
        for (int b = 0; b < 8; b++)
#pragma unroll
            for (int c = 0; c < 4; c++) acc[a][b][c] = 0.0f;

    // ---- stage issue (16 cp.async per thread) ----
    auto issue_stage = [&](int k0h, uint32_t sOff) {
#pragma unroll
        for (int i = 0; i < 8; i++)
            cp16(smem_u32 + sOff + dsto[i], baseA + off[i] + k0h);
#pragma unroll
        for (int i = 0; i < 8; i++)
            cp16(smem_u32 + STAGE_A + sOff + dsto[i], baseB + off[i] + k0h);
        asm volatile("cp.async.commit_group;\n" ::: "memory");
    };

    issue_stage(0, 0);
    issue_stage(64, STAGE_BYTES);

    uint32_t fA[2][4][4], fB[2][4][4];

#pragma unroll 1
    for (int k = 0; k < KT; k++) {
        if (k < KT - 1) asm volatile("cp.async.wait_group 1;\n" ::: "memory");
        else            asm volatile("cp.async.wait_group 0;\n" ::: "memory");
        __syncthreads();

        uint32_t sA = smem_u32 + (uint32_t)(k % STAGES) * STAGE_BYTES;
        uint32_t sB = sA + STAGE_A;

        // prime kstep 0 fragments
#pragma unroll
        for (int t4 = 0; t4 < 4; t4++)
            ldsm_x4(fA[0][t4], sA + aOff[t4] + (uint32_t)((hi ^ aSw[t4]) << 4));
#pragma unroll
        for (int p = 0; p < 4; p++)
            ldsm_x4(fB[0][p], sB + bOff[p] + (uint32_t)((piece ^ bSw[p]) << 4));

#pragma unroll
        for (int ks = 0; ks < 4; ks++) {
            int cb = ks & 1, nb = cb ^ 1;
            if (ks < 3) {
                int kc = (ks + 1) << 1;
#pragma unroll
                for (int t4 = 0; t4 < 4; t4++)
                    ldsm_x4(fA[nb][t4], sA + aOff[t4] + (uint32_t)(((kc + hi) ^ aSw[t4]) << 4));
#pragma unroll
                for (int p = 0; p < 4; p++)
                    ldsm_x4(fB[nb][p], sB + bOff[p] + (uint32_t)(((kc + piece) ^ bSw[p]) << 4));
            } else if (k + 2 < KT) {
                issue_stage((k + 2) * 64, (uint32_t)((k + 2) % STAGES) * STAGE_BYTES);
            }
#pragma unroll
            for (int t4 = 0; t4 < 4; t4++)
#pragma unroll
                for (int p = 0; p < 4; p++) {
                    mma16816(acc[t4][2 * p],     fA[cb][t4], &fB[cb][p][0]);
                    mma16816(acc[t4][2 * p + 1], fA[cb][t4], &fB[cb][p][2]);
                }
        }
    }

    // -------- epilogue: acc -> smem (transpose to n-contiguous) --------
    __syncthreads();   // all compute done; stage smem now reusable
#pragma unroll
    for (int t4 = 0; t4 < 4; t4++) {
#pragma unroll
        for (int p = 0; p < 4; p++) {
            int r0 = wm * 64 + t4 * 16 + (lane >> 2);
            int c0 = wn * 64 + p * 16 + (lane & 3) * 2;
            *(float2*)&smemf[r0 * EPI_STRIDE + c0]            = make_float2(acc[t4][2 * p][0], acc[t4][2 * p][1]);
            *(float2*)&smemf[(r0 + 8) * EPI_STRIDE + c0]      = make_float2(acc[t4][2 * p][2], acc[t4][2 * p][3]);
            *(float2*)&smemf[r0 * EPI_STRIDE + c0 + 8]        = make_float2(acc[t4][2 * p + 1][0], acc[t4][2 * p + 1][1]);
            *(float2*)&smemf[(r0 + 8) * EPI_STRIDE + c0 + 8]  = make_float2(acc[t4][2 * p + 1][2], acc[t4][2 * p + 1][3]);
        }
    }
    __syncthreads();

    // -------- fused LSTM: gates -> h_t, c_t --------
    int r = tid;                      // 0..127 (batch row within tile)
    int mrow = m0 + r;
    int hglob0 = nt * 32;             // this block's head range (BN/4 = 32 heads)
    const float* cpr = c_prev + (size_t)mrow * HSZ + hglob0;
    float* hout = out + (size_t)mrow * HSZ + hglob0;
    float* cout = out + (size_t)BATCH * HSZ + (size_t)mrow * HSZ + hglob0;
    const float* biasf = (const float*)(smem + BIAS_OFF);
#pragma unroll
    for (int g4 = 0; g4 < 8; g4++) {
        int hl = g4 * 4;                               // local head base
        float4 cp4 = *(const float4*)(cpr + hl);
        float cpv[4] = {cp4.x, cp4.y, cp4.z, cp4.w};
        float hv[4], cv[4];
#pragma unroll
        for (int j = 0; j < 4; j++) {
            const float* gt = &smemf[r * EPI_STRIDE + (hl + j) * 4];
            const float* bs = &biasf[(hl + j) * 4];
            float gf = gt[0] + bs[0];
            float gi = gt[1] + bs[1];
            float gc = gt[2] + bs[2];
            float go = gt[3] + bs[3];
            float f  = sigmoidf_(gf);
            float iv = sigmoidf_(gi);
            float ct = tanhf_(gc);
            float o  = sigmoidf_(go);
            float cn = fmaf(f, cpv[j], iv * ct);
            cv[j] = cn;
            hv[j] = o * tanhf_(cn);
        }
        *(float4*)(hout + hl) = make_float4(hv[0], hv[1], hv[2], hv[3]);
        *(float4*)(cout + hl) = make_float4(cv[0], cv[1], cv[2], cv[3]);
    }
}

// ---------------- launch ----------------
extern "C" void kernel_launch(void* const* d_in, const int* in_sizes, int n_in,
                              void* d_out, int out_size) {
    const float* x  = (const float*)d_in[0];
    const float* h  = (const float*)d_in[1];
    const float* c  = (const float*)d_in[2];
    const float* Wf = (const float*)d_in[3];
    const float* bf = (const float*)d_in[4];
    const float* Wi = (const float*)d_in[5];
    const float* bi = (const float*)d_in[6];
    const float* Wc = (const float*)d_in[7];
    const float* bc = (const float*)d_in[8];
    const float* Wo = (const float*)d_in[9];
    const float* bo = (const float*)d_in[10];
    float* out = (float*)d_out;

    conv_a_kernel<<<(BATCH * KDIM / 4) / 256, 256>>>(x, h);
    conv_w_kernel<<<(NDIM * KDIM / 4) / 256, 256>>>(Wf, Wi, Wc, Wo);
    conv_b_kernel<<<NDIM / 256, 256>>>(bf, bi, bc, bo);

    static int smem_set = 0;
    if (!smem_set) {
        cudaFuncSetAttribute(lstm_gemm_kernel,
                             cudaFuncAttributeMaxDynamicSharedMemorySize, SMEM_TOTAL);
        smem_set = 1;
    }
    lstm_gemm_kernel<<<(BATCH / BM) * (NDIM / BN), NTHREADS, SMEM_TOTAL>>>(c, out);
}